// round 1
// baseline (speedup 1.0000x reference)
#include <cuda_runtime.h>
#include <cuda_bf16.h>
#include <cstdint>

#define NN 1024
#define DD 512
#define CC 384
#define SS 49
#define NCS (NN*CC*SS)   // 19267584

// scratch (static device arrays — no runtime allocation)
__device__ __align__(16) __nv_bfloat16 g_f[NN*DD];
__device__ __align__(16) __nv_bfloat16 g_pos[(size_t)SS*NN*DD];
__device__ __align__(16) __nv_bfloat16 g_pred[(size_t)SS*NN*DD];
__device__ float g_ce[2*SS*8];

// ---------------------------------------------------------------------------
// convert f_t_global -> bf16
__global__ void k_convert_f(const float* __restrict__ f) {
    int i = blockIdx.x * blockDim.x + threadIdx.x;
    if (i < NN*DD) g_f[i] = __float2bfloat16(f[i]);
}

// ---------------------------------------------------------------------------
// Build spatial part of pos/pred: dst[s][j][d] = x[j][d][s] (d<384), bf16.
// Also streams the raw fp32 copy of x into the output buffer.
__global__ void k_spatial(const float* __restrict__ x,
                          float* __restrict__ outCopy,
                          int isPred) {
    __shared__ float sbuf[32*SS];
    __nv_bfloat16* dst = isPred ? g_pred : g_pos;
    int j = blockIdx.x;
    const float* xj = x + (size_t)j*CC*SS;
    float* oj = outCopy + (size_t)j*CC*SS;
    for (int d0 = 0; d0 < CC; d0 += 32) {
        for (int t = threadIdx.x; t < 32*SS; t += blockDim.x) {
            float v = xj[d0*SS + t];
            sbuf[t] = v;
            oj[d0*SS + t] = v;
        }
        __syncthreads();
        for (int t = threadIdx.x; t < 32*SS; t += blockDim.x) {
            int ss = t >> 5;
            int dd = t & 31;
            dst[((size_t)(ss*NN + j))*DD + d0 + dd] = __float2bfloat16(sbuf[dd*SS + ss]);
        }
        __syncthreads();
    }
}

// ---------------------------------------------------------------------------
// Build m/c part: dst[s][j][384+dd] = (dd<64 ? m[j][dd] : c[j][dd-64]) for all s
__global__ void k_mc(const float* __restrict__ m, const float* __restrict__ c,
                     int isPred) {
    __nv_bfloat16* dst = isPred ? g_pred : g_pos;
    int j = blockIdx.x;
    int dd = threadIdx.x;  // 0..127
    float v = (dd < 64) ? m[j*64 + dd] : c[j*64 + dd - 64];
    __nv_bfloat16 bv = __float2bfloat16(v);
    for (int s = 0; s < SS; s++)
        dst[((size_t)(s*NN + j))*DD + CC + dd] = bv;
}

// ---------------------------------------------------------------------------
// Fused GEMM + online logsumexp. Grid: (iTile 0..7, s 0..48, which 0..1).
// CTA tile 128 (i) x 128 (j), K=512, bf16 mma.sync m16n8k16, fp32 accum.
// Warp layout: 8 warps as 2 (rows of 64) x 4 (cols of 32).
__global__ void __launch_bounds__(256) k_main() {
    const int iTile = blockIdx.x;
    const int s     = blockIdx.y;
    const int which = blockIdx.z;
    const int tid  = threadIdx.x;
    const int lane = tid & 31;
    const int warp = tid >> 5;
    const int wRow = warp >> 2;   // 0..1
    const int wCol = warp & 3;    // 0..3
    const int iBase = iTile * 128;

    __shared__ __align__(16) __nv_bfloat16 sA[128][72];
    __shared__ __align__(16) __nv_bfloat16 sB[128][72];
    __shared__ float sM[128][4];
    __shared__ float sL[128][4];
    __shared__ float sDiag[128];
    __shared__ float sRed[8];

    const __nv_bfloat16* gA = which ? (g_pred + ((size_t)(s*NN) + iBase) * DD)
                                    : (g_f + (size_t)iBase * DD);
    const __nv_bfloat16* gB0 = g_pos + (size_t)(s*NN) * DD;

    float rm[4][2], rl[4][2];
    #pragma unroll
    for (int mf = 0; mf < 4; mf++)
        #pragma unroll
        for (int h = 0; h < 2; h++) { rm[mf][h] = -1e30f; rl[mf][h] = 0.f; }

    for (int jt = 0; jt < 8; ++jt) {
        float acc[4][4][4];
        #pragma unroll
        for (int mf = 0; mf < 4; mf++)
            #pragma unroll
            for (int nf = 0; nf < 4; nf++)
                #pragma unroll
                for (int v = 0; v < 4; v++) acc[mf][nf][v] = 0.f;

        const __nv_bfloat16* gB = gB0 + (size_t)jt * 128 * DD;

        for (int kt = 0; kt < 8; ++kt) {
            __syncthreads();
            #pragma unroll
            for (int p = 0; p < 4; ++p) {
                int id = tid + p * 256;
                int r  = id >> 3;
                int ck = id & 7;
                const int4* srcA = reinterpret_cast<const int4*>(gA + (size_t)r*DD + kt*64) + ck;
                *reinterpret_cast<int4*>(&sA[r][ck*8]) = *srcA;
                const int4* srcB = reinterpret_cast<const int4*>(gB + (size_t)r*DD + kt*64) + ck;
                *reinterpret_cast<int4*>(&sB[r][ck*8]) = *srcB;
            }
            __syncthreads();

            #pragma unroll
            for (int ks = 0; ks < 4; ++ks) {
                uint32_t aF[4][4], bF[4][2];
                #pragma unroll
                for (int mf = 0; mf < 4; mf++) {
                    int row = wRow*64 + mf*16 + (lane & 15);
                    int col = ks*16 + ((lane >> 4) << 3);
                    uint32_t addr = (uint32_t)__cvta_generic_to_shared(&sA[row][col]);
                    asm volatile("ldmatrix.sync.aligned.m8n8.x4.shared.b16 {%0,%1,%2,%3}, [%4];"
                        : "=r"(aF[mf][0]), "=r"(aF[mf][1]), "=r"(aF[mf][2]), "=r"(aF[mf][3])
                        : "r"(addr));
                }
                #pragma unroll
                for (int nf = 0; nf < 4; nf++) {
                    int row = wCol*32 + nf*8 + (lane & 7);
                    int col = ks*16 + (((lane >> 3) & 1) << 3);
                    uint32_t addr = (uint32_t)__cvta_generic_to_shared(&sB[row][col]);
                    asm volatile("ldmatrix.sync.aligned.m8n8.x2.shared.b16 {%0,%1}, [%2];"
                        : "=r"(bF[nf][0]), "=r"(bF[nf][1])
                        : "r"(addr));
                }
                #pragma unroll
                for (int mf = 0; mf < 4; mf++)
                    #pragma unroll
                    for (int nf = 0; nf < 4; nf++) {
                        float* c = acc[mf][nf];
                        asm volatile("mma.sync.aligned.m16n8k16.row.col.f32.bf16.bf16.f32 "
                            "{%0,%1,%2,%3}, {%4,%5,%6,%7}, {%8,%9}, {%0,%1,%2,%3};"
                            : "+f"(c[0]), "+f"(c[1]), "+f"(c[2]), "+f"(c[3])
                            : "r"(aF[mf][0]), "r"(aF[mf][1]), "r"(aF[mf][2]), "r"(aF[mf][3]),
                              "r"(bF[nf][0]), "r"(bF[nf][1]));
                    }
            }
        }

        // Online softmax update for this 128-col j-tile.
        bool diagTile = (jt == iTile);
        #pragma unroll
        for (int mf = 0; mf < 4; mf++) {
            #pragma unroll
            for (int h = 0; h < 2; h++) {
                float tm = -1e30f;
                #pragma unroll
                for (int nf = 0; nf < 4; nf++) {
                    tm = fmaxf(tm, acc[mf][nf][h*2]);
                    tm = fmaxf(tm, acc[mf][nf][h*2+1]);
                }
                tm = fmaxf(tm, __shfl_xor_sync(0xffffffffu, tm, 1));
                tm = fmaxf(tm, __shfl_xor_sync(0xffffffffu, tm, 2));
                float mn = fmaxf(rm[mf][h], tm);
                float p = 0.f;
                #pragma unroll
                for (int nf = 0; nf < 4; nf++) {
                    p += __expf(acc[mf][nf][h*2]   - mn);
                    p += __expf(acc[mf][nf][h*2+1] - mn);
                }
                p += __shfl_xor_sync(0xffffffffu, p, 1);
                p += __shfl_xor_sync(0xffffffffu, p, 2);
                rl[mf][h] = rl[mf][h] * __expf(rm[mf][h] - mn) + p;
                rm[mf][h] = mn;
                if (diagTile) {
                    int rowLocal = wRow*64 + mf*16 + h*8 + (lane >> 2);
                    #pragma unroll
                    for (int nf = 0; nf < 4; nf++) {
                        #pragma unroll
                        for (int q = 0; q < 2; q++) {
                            int col = wCol*32 + nf*8 + (lane & 3)*2 + q;
                            if (col == rowLocal) sDiag[rowLocal] = acc[mf][nf][h*2+q];
                        }
                    }
                }
            }
        }
    }

    // Combine across the 4 warp-columns.
    if ((lane & 3) == 0) {
        #pragma unroll
        for (int mf = 0; mf < 4; mf++)
            #pragma unroll
            for (int h = 0; h < 2; h++) {
                int rowLocal = wRow*64 + mf*16 + h*8 + (lane >> 2);
                sM[rowLocal][wCol] = rm[mf][h];
                sL[rowLocal][wCol] = rl[mf][h];
            }
    }
    __syncthreads();

    float ce = 0.f;
    if (tid < 128) {
        float M = fmaxf(fmaxf(sM[tid][0], sM[tid][1]), fmaxf(sM[tid][2], sM[tid][3]));
        float L = 0.f;
        #pragma unroll
        for (int w = 0; w < 4; w++) L += sL[tid][w] * __expf(sM[tid][w] - M);
        ce = M + logf(L) - sDiag[tid];
    }
    #pragma unroll
    for (int o = 16; o > 0; o >>= 1) ce += __shfl_xor_sync(0xffffffffu, ce, o);
    if (lane == 0) sRed[warp] = ce;
    __syncthreads();
    if (tid == 0) {
        float t = 0.f;
        #pragma unroll
        for (int w = 0; w < 8; w++) t += sRed[w];
        g_ce[(which*SS + s)*8 + iTile] = t;
    }
}

// ---------------------------------------------------------------------------
__global__ void k_final(float* __restrict__ out) {
    __shared__ float sr[8];
    int tid = threadIdx.x;
    float s = 0.f;
    for (int i = tid; i < 2*SS*8; i += 256) s += g_ce[i];
    #pragma unroll
    for (int o = 16; o > 0; o >>= 1) s += __shfl_xor_sync(0xffffffffu, s, o);
    if ((tid & 31) == 0) sr[tid >> 5] = s;
    __syncthreads();
    if (tid == 0) {
        float t = 0.f;
        #pragma unroll
        for (int w = 0; w < 8; w++) t += sr[w];
        out[0] = t / (float)(SS * NN);
    }
}

// ---------------------------------------------------------------------------
extern "C" void kernel_launch(void* const* d_in, const int* in_sizes, int n_in,
                              void* d_out, int out_size) {
    const float* f  = (const float*)d_in[0];  // f_t_global      [1024,512]
    const float* xc = (const float*)d_in[1];  // x_t_local       [1024,384,7,7]
    const float* xp = (const float*)d_in[2];  // x_t_prev_local  [1024,384,7,7]
    const float* mt = (const float*)d_in[3];  // m_t             [1024,64]
    const float* mp = (const float*)d_in[4];  // m_t_prev        [1024,64]
    const float* ct = (const float*)d_in[5];  // c_t             [1024,64]
    const float* cp = (const float*)d_in[6];  // c_t_prev        [1024,64]
    float* out = (float*)d_out;               // [1 + 2*NCS] fp32: loss, x_prev, x_cur

    k_convert_f<<<(NN*DD + 255)/256, 256>>>(f);
    k_spatial<<<NN, 256>>>(xp, out + 1, 0);            // pos spatial + prev copy
    k_spatial<<<NN, 256>>>(xc, out + 1 + (size_t)NCS, 1); // pred spatial + cur copy
    k_mc<<<NN, 128>>>(mp, cp, 0);
    k_mc<<<NN, 128>>>(mt, ct, 1);
    k_main<<<dim3(8, SS, 2), 256>>>();
    k_final<<<1, 256>>>(out);
}

// round 2
// speedup vs baseline: 1.1737x; 1.1737x over previous
#include <cuda_runtime.h>
#include <cuda_bf16.h>
#include <cstdint>

#define NN 1024
#define DD 512
#define CC 384
#define SS 49
#define NCS (NN*CC*SS)   // 19267584

// ---------------------------------------------------------------------------
// scratch (static device arrays — no runtime allocation)
__device__ __align__(16) __nv_bfloat16 g_fs[NN*CC];                 // f[:,0:384]
__device__ __align__(16) __nv_bfloat16 g_fm[NN*128];                // f[:,384:512]
__device__ __align__(16) __nv_bfloat16 g_prev[(size_t)SS*NN*CC];    // pos spatial
__device__ __align__(16) __nv_bfloat16 g_cur[(size_t)SS*NN*CC];     // pred spatial
__device__ __align__(16) __nv_bfloat16 g_mcp[NN*128];               // [m_prev,c_prev]
__device__ __align__(16) __nv_bfloat16 g_mcc[NN*128];               // [m_t,c_t]
__device__ float g_bias[2][NN*NN];                                  // 8MB fp32
__device__ float g_ce[2*SS*8];

__device__ __forceinline__ void cp16(void* dst, const void* src) {
    uint32_t d = (uint32_t)__cvta_generic_to_shared(dst);
    asm volatile("cp.async.cg.shared.global [%0], [%1], 16;\n" :: "r"(d), "l"(src));
}

// ---------------------------------------------------------------------------
__global__ void k_convert_f(const float* __restrict__ f) {
    int i = blockIdx.x * blockDim.x + threadIdx.x;
    if (i >= NN*DD) return;
    int row = i >> 9, d = i & 511;
    __nv_bfloat16 v = __float2bfloat16(f[i]);
    if (d < CC) g_fs[row*CC + d];
    if (d < CC) g_fs[row*CC + d] = v; else g_fm[row*128 + d - CC] = v;
}

// dst[s][j][d] = x[j][d][s] (d<384), bf16; also raw fp32 copy to out.
__global__ void k_spatial(const float* __restrict__ x,
                          float* __restrict__ outCopy,
                          int isPred) {
    __shared__ float sbuf[32*SS];
    __nv_bfloat16* dst = isPred ? g_cur : g_prev;
    int j = blockIdx.x;
    const float* xj = x + (size_t)j*CC*SS;
    float* oj = outCopy + (size_t)j*CC*SS;
    for (int d0 = 0; d0 < CC; d0 += 32) {
        for (int t = threadIdx.x; t < 32*SS; t += blockDim.x) {
            float v = xj[d0*SS + t];
            sbuf[t] = v;
            oj[d0*SS + t] = v;
        }
        __syncthreads();
        for (int t = threadIdx.x; t < 32*SS; t += blockDim.x) {
            int ss = t >> 5;
            int dd = t & 31;
            dst[((size_t)(ss*NN + j))*CC + d0 + dd] = __float2bfloat16(sbuf[dd*SS + ss]);
        }
        __syncthreads();
    }
}

__global__ void k_mc(const float* __restrict__ mp, const float* __restrict__ cp,
                     const float* __restrict__ mt, const float* __restrict__ ct) {
    int j = blockIdx.x;
    int dd = threadIdx.x;  // 0..127
    float vp = (dd < 64) ? mp[j*64 + dd] : cp[j*64 + dd - 64];
    float vc = (dd < 64) ? mt[j*64 + dd] : ct[j*64 + dd - 64];
    g_mcp[j*128 + dd] = __float2bfloat16(vp);
    g_mcc[j*128 + dd] = __float2bfloat16(vc);
}

// ---------------------------------------------------------------------------
// bias[which][i][j] = (which? mcc[i] : fm[i]) . mcp[j], K=128. grid (8,8,2).
__global__ void __launch_bounds__(256) k_bias() {
    const int iBase = blockIdx.x * 128;
    const int jBase = blockIdx.y * 128;
    const int which = blockIdx.z;
    const int tid  = threadIdx.x;
    const int lane = tid & 31;
    const int warp = tid >> 5;
    const int wRow = warp >> 2;
    const int wCol = warp & 3;

    __shared__ __align__(16) __nv_bfloat16 sA[128][72];
    __shared__ __align__(16) __nv_bfloat16 sB[128][72];

    const __nv_bfloat16* gA = (which ? g_mcc : g_fm) + (size_t)iBase * 128;
    const __nv_bfloat16* gB = g_mcp + (size_t)jBase * 128;

    float acc[4][4][4];
    #pragma unroll
    for (int mf = 0; mf < 4; mf++)
        #pragma unroll
        for (int nf = 0; nf < 4; nf++)
            #pragma unroll
            for (int v = 0; v < 4; v++) acc[mf][nf][v] = 0.f;

    for (int kt = 0; kt < 2; ++kt) {
        __syncthreads();
        #pragma unroll
        for (int p = 0; p < 4; ++p) {
            int id = tid + p * 256;
            int r  = id >> 3;
            int ck = id & 7;
            *reinterpret_cast<int4*>(&sA[r][ck*8]) =
                *(reinterpret_cast<const int4*>(gA + (size_t)r*128 + kt*64) + ck);
            *reinterpret_cast<int4*>(&sB[r][ck*8]) =
                *(reinterpret_cast<const int4*>(gB + (size_t)r*128 + kt*64) + ck);
        }
        __syncthreads();
        #pragma unroll
        for (int ks = 0; ks < 4; ++ks) {
            uint32_t aF[4][4], bF[4][2];
            #pragma unroll
            for (int mf = 0; mf < 4; mf++) {
                int row = wRow*64 + mf*16 + (lane & 15);
                int col = ks*16 + ((lane >> 4) << 3);
                uint32_t addr = (uint32_t)__cvta_generic_to_shared(&sA[row][col]);
                asm volatile("ldmatrix.sync.aligned.m8n8.x4.shared.b16 {%0,%1,%2,%3}, [%4];"
                    : "=r"(aF[mf][0]), "=r"(aF[mf][1]), "=r"(aF[mf][2]), "=r"(aF[mf][3])
                    : "r"(addr));
            }
            #pragma unroll
            for (int nf = 0; nf < 4; nf++) {
                int row = wCol*32 + nf*8 + (lane & 7);
                int col = ks*16 + (((lane >> 3) & 1) << 3);
                uint32_t addr = (uint32_t)__cvta_generic_to_shared(&sB[row][col]);
                asm volatile("ldmatrix.sync.aligned.m8n8.x2.shared.b16 {%0,%1}, [%2];"
                    : "=r"(bF[nf][0]), "=r"(bF[nf][1]) : "r"(addr));
            }
            #pragma unroll
            for (int mf = 0; mf < 4; mf++)
                #pragma unroll
                for (int nf = 0; nf < 4; nf++) {
                    float* c = acc[mf][nf];
                    asm volatile("mma.sync.aligned.m16n8k16.row.col.f32.bf16.bf16.f32 "
                        "{%0,%1,%2,%3}, {%4,%5,%6,%7}, {%8,%9}, {%0,%1,%2,%3};"
                        : "+f"(c[0]), "+f"(c[1]), "+f"(c[2]), "+f"(c[3])
                        : "r"(aF[mf][0]), "r"(aF[mf][1]), "r"(aF[mf][2]), "r"(aF[mf][3]),
                          "r"(bF[nf][0]), "r"(bF[nf][1]));
                }
        }
    }

    float* gOut = g_bias[which];
    #pragma unroll
    for (int mf = 0; mf < 4; mf++)
        #pragma unroll
        for (int h = 0; h < 2; h++) {
            int row = iBase + wRow*64 + mf*16 + h*8 + (lane >> 2);
            #pragma unroll
            for (int nf = 0; nf < 4; nf++) {
                int col = jBase + wCol*32 + nf*8 + (lane & 3)*2;
                float2 v = make_float2(acc[mf][nf][h*2], acc[mf][nf][h*2+1]);
                *reinterpret_cast<float2*>(gOut + (size_t)row*NN + col) = v;
            }
        }
}

// ---------------------------------------------------------------------------
// Fused GEMM(K=384) + bias + online logsumexp. Grid: (iTile 0..7, s, which).
// A resident in smem; B triple-buffered via cp.async, depth-2 prefetch.
#define SA_STRIDE 392
#define SB_STRIDE 72
#define OFF_SB   (128*SA_STRIDE*2)                  // 100352
#define OFF_SM   (OFF_SB + 3*128*SB_STRIDE*2)       // 155648
#define OFF_SL   (OFF_SM + 128*4*4)
#define OFF_SD   (OFF_SL + 128*4*4)
#define OFF_SR   (OFF_SD + 128*4)
#define SMEM_MAIN (OFF_SR + 8*4)                    // 160288

__global__ void __launch_bounds__(256) k_main() {
    extern __shared__ char smraw[];
    __nv_bfloat16 (*sA)[SA_STRIDE] =
        reinterpret_cast<__nv_bfloat16(*)[SA_STRIDE]>(smraw);
    __nv_bfloat16 (*sB)[128][SB_STRIDE] =
        reinterpret_cast<__nv_bfloat16(*)[128][SB_STRIDE]>(smraw + OFF_SB);
    float (*sM)[4] = reinterpret_cast<float(*)[4]>(smraw + OFF_SM);
    float (*sL)[4] = reinterpret_cast<float(*)[4]>(smraw + OFF_SL);
    float* sDiag   = reinterpret_cast<float*>(smraw + OFF_SD);
    float* sRed    = reinterpret_cast<float*>(smraw + OFF_SR);

    const int iTile = blockIdx.x;
    const int s     = blockIdx.y;
    const int which = blockIdx.z;
    const int tid  = threadIdx.x;
    const int lane = tid & 31;
    const int warp = tid >> 5;
    const int wRow = warp >> 2;
    const int wCol = warp & 3;
    const int iBase = iTile * 128;

    const __nv_bfloat16* gA = which ? (g_cur + ((size_t)(s*NN) + iBase) * CC)
                                    : (g_fs + (size_t)iBase * CC);
    const __nv_bfloat16* gB0 = g_prev + (size_t)(s*NN) * CC;
    const float* gBias = g_bias[which] + (size_t)iBase * NN;

    // A: 128 rows x 384 cols -> 6144 int4; 24 per thread. group 0.
    #pragma unroll
    for (int p = 0; p < 24; ++p) {
        int id = tid + p * 256;
        int r = id / 48;
        int ck = id % 48;
        cp16(&sA[r][ck*8], gA + (size_t)r*CC + ck*8);
    }
    asm volatile("cp.async.commit_group;");

    // B chunk loader: chunk c -> (jt=c/6, kt=c%6)
    auto loadB = [&](int c) {
        int jt = c / 6, kt = c % 6;
        int buf = c % 3;
        const __nv_bfloat16* src = gB0 + (size_t)jt*128*CC + kt*64;
        #pragma unroll
        for (int p = 0; p < 4; ++p) {
            int id = tid + p * 256;
            int r = id >> 3, ck = id & 7;
            cp16(&sB[buf][r][ck*8], src + (size_t)r*CC + ck*8);
        }
        asm volatile("cp.async.commit_group;");
    };

    loadB(0);
    loadB(1);

    float rm[4][2], rl[4][2];
    #pragma unroll
    for (int mf = 0; mf < 4; mf++)
        #pragma unroll
        for (int h = 0; h < 2; h++) { rm[mf][h] = -1e30f; rl[mf][h] = 0.f; }

    int c = 0;
    for (int jt = 0; jt < 8; ++jt) {
        float acc[4][4][4];
        #pragma unroll
        for (int mf = 0; mf < 4; mf++)
            #pragma unroll
            for (int nf = 0; nf < 4; nf++)
                #pragma unroll
                for (int v = 0; v < 4; v++) acc[mf][nf][v] = 0.f;

        for (int kt = 0; kt < 6; ++kt, ++c) {
            if (c == 47) asm volatile("cp.async.wait_group 0;");
            else         asm volatile("cp.async.wait_group 1;");
            __syncthreads();
            if (c + 2 < 48) loadB(c + 2);

            const int buf = c % 3;
            #pragma unroll
            for (int ks = 0; ks < 4; ++ks) {
                uint32_t aF[4][4], bF[4][2];
                #pragma unroll
                for (int mf = 0; mf < 4; mf++) {
                    int row = wRow*64 + mf*16 + (lane & 15);
                    int col = kt*64 + ks*16 + ((lane >> 4) << 3);
                    uint32_t addr = (uint32_t)__cvta_generic_to_shared(&sA[row][col]);
                    asm volatile("ldmatrix.sync.aligned.m8n8.x4.shared.b16 {%0,%1,%2,%3}, [%4];"
                        : "=r"(aF[mf][0]), "=r"(aF[mf][1]), "=r"(aF[mf][2]), "=r"(aF[mf][3])
                        : "r"(addr));
                }
                #pragma unroll
                for (int nf = 0; nf < 4; nf++) {
                    int row = wCol*32 + nf*8 + (lane & 7);
                    int col = ks*16 + (((lane >> 3) & 1) << 3);
                    uint32_t addr = (uint32_t)__cvta_generic_to_shared(&sB[buf][row][col]);
                    asm volatile("ldmatrix.sync.aligned.m8n8.x2.shared.b16 {%0,%1}, [%2];"
                        : "=r"(bF[nf][0]), "=r"(bF[nf][1]) : "r"(addr));
                }
                #pragma unroll
                for (int mf = 0; mf < 4; mf++)
                    #pragma unroll
                    for (int nf = 0; nf < 4; nf++) {
                        float* cc = acc[mf][nf];
                        asm volatile("mma.sync.aligned.m16n8k16.row.col.f32.bf16.bf16.f32 "
                            "{%0,%1,%2,%3}, {%4,%5,%6,%7}, {%8,%9}, {%0,%1,%2,%3};"
                            : "+f"(cc[0]), "+f"(cc[1]), "+f"(cc[2]), "+f"(cc[3])
                            : "r"(aF[mf][0]), "r"(aF[mf][1]), "r"(aF[mf][2]), "r"(aF[mf][3]),
                              "r"(bF[nf][0]), "r"(bF[nf][1]));
                    }
            }
        }

        // bias add (fp32, L2-resident)
        #pragma unroll
        for (int mf = 0; mf < 4; mf++)
            #pragma unroll
            for (int h = 0; h < 2; h++) {
                int row = wRow*64 + mf*16 + h*8 + (lane >> 2);
                const float2* bp = reinterpret_cast<const float2*>(
                    gBias + (size_t)row*NN + jt*128 + wCol*32 + (lane & 3)*2);
                #pragma unroll
                for (int nf = 0; nf < 4; nf++) {
                    float2 b = __ldg(bp + nf*4);
                    acc[mf][nf][h*2]   += b.x;
                    acc[mf][nf][h*2+1] += b.y;
                }
            }

        // online softmax update
        bool diagTile = (jt == iTile);
        #pragma unroll
        for (int mf = 0; mf < 4; mf++) {
            #pragma unroll
            for (int h = 0; h < 2; h++) {
                float tm = -1e30f;
                #pragma unroll
                for (int nf = 0; nf < 4; nf++) {
                    tm = fmaxf(tm, acc[mf][nf][h*2]);
                    tm = fmaxf(tm, acc[mf][nf][h*2+1]);
                }
                tm = fmaxf(tm, __shfl_xor_sync(0xffffffffu, tm, 1));
                tm = fmaxf(tm, __shfl_xor_sync(0xffffffffu, tm, 2));
                float mn = fmaxf(rm[mf][h], tm);
                float p = 0.f;
                #pragma unroll
                for (int nf = 0; nf < 4; nf++) {
                    p += __expf(acc[mf][nf][h*2]   - mn);
                    p += __expf(acc[mf][nf][h*2+1] - mn);
                }
                p += __shfl_xor_sync(0xffffffffu, p, 1);
                p += __shfl_xor_sync(0xffffffffu, p, 2);
                rl[mf][h] = rl[mf][h] * __expf(rm[mf][h] - mn) + p;
                rm[mf][h] = mn;
                if (diagTile) {
                    int rowLocal = wRow*64 + mf*16 + h*8 + (lane >> 2);
                    #pragma unroll
                    for (int nf = 0; nf < 4; nf++) {
                        #pragma unroll
                        for (int q = 0; q < 2; q++) {
                            int col = wCol*32 + nf*8 + (lane & 3)*2 + q;
                            if (col == rowLocal) sDiag[rowLocal] = acc[mf][nf][h*2+q];
                        }
                    }
                }
            }
        }
    }

    if ((lane & 3) == 0) {
        #pragma unroll
        for (int mf = 0; mf < 4; mf++)
            #pragma unroll
            for (int h = 0; h < 2; h++) {
                int rowLocal = wRow*64 + mf*16 + h*8 + (lane >> 2);
                sM[rowLocal][wCol] = rm[mf][h];
                sL[rowLocal][wCol] = rl[mf][h];
            }
    }
    __syncthreads();

    float ce = 0.f;
    if (tid < 128) {
        float M = fmaxf(fmaxf(sM[tid][0], sM[tid][1]), fmaxf(sM[tid][2], sM[tid][3]));
        float L = 0.f;
        #pragma unroll
        for (int w = 0; w < 4; w++) L += sL[tid][w] * __expf(sM[tid][w] - M);
        ce = M + logf(L) - sDiag[tid];
    }
    #pragma unroll
    for (int o = 16; o > 0; o >>= 1) ce += __shfl_xor_sync(0xffffffffu, ce, o);
    if (lane == 0) sRed[warp] = ce;
    __syncthreads();
    if (tid == 0) {
        float t = 0.f;
        #pragma unroll
        for (int w = 0; w < 8; w++) t += sRed[w];
        g_ce[(which*SS + s)*8 + iTile] = t;
    }
}

// ---------------------------------------------------------------------------
__global__ void k_final(float* __restrict__ out) {
    __shared__ float sr[8];
    int tid = threadIdx.x;
    float s = 0.f;
    for (int i = tid; i < 2*SS*8; i += 256) s += g_ce[i];
    #pragma unroll
    for (int o = 16; o > 0; o >>= 1) s += __shfl_xor_sync(0xffffffffu, s, o);
    if ((tid & 31) == 0) sr[tid >> 5] = s;
    __syncthreads();
    if (tid == 0) {
        float t = 0.f;
        #pragma unroll
        for (int w = 0; w < 8; w++) t += sr[w];
        out[0] = t / (float)(SS * NN);
    }
}

// ---------------------------------------------------------------------------
extern "C" void kernel_launch(void* const* d_in, const int* in_sizes, int n_in,
                              void* d_out, int out_size) {
    const float* f  = (const float*)d_in[0];
    const float* xc = (const float*)d_in[1];
    const float* xp = (const float*)d_in[2];
    const float* mt = (const float*)d_in[3];
    const float* mp = (const float*)d_in[4];
    const float* ct = (const float*)d_in[5];
    const float* cp = (const float*)d_in[6];
    float* out = (float*)d_out;

    cudaFuncSetAttribute(k_main, cudaFuncAttributeMaxDynamicSharedMemorySize, SMEM_MAIN);

    k_convert_f<<<(NN*DD + 255)/256, 256>>>(f);
    k_spatial<<<NN, 256>>>(xp, out + 1, 0);
    k_spatial<<<NN, 256>>>(xc, out + 1 + (size_t)NCS, 1);
    k_mc<<<NN, 128>>>(mp, cp, mt, ct);
    k_bias<<<dim3(8, 8, 2), 256>>>();
    k_main<<<dim3(8, SS, 2), 256, SMEM_MAIN>>>();
    k_final<<<1, 256>>>(out);
}